// round 14
// baseline (speedup 1.0000x reference)
#include <cuda_runtime.h>
#include <cuda_bf16.h>
#include <cstdint>

// KDE via bf16 HMMA (mma.sync m16n8k16) GEMM over K=384 (2-term fp32 split):
//   Xcat[n] = [hiX | hiX | loX], Dcat[m] = [hiD | loD | hiD]
// density[n] = (1/M) * sum_m exp2( KEXP*(||x||^2+||d||^2) + K2*dot )
// R9: 128-thread CTAs, 2x2 warp grid, 64x64 warp tile -> smem LDSM traffic
// cut 33% (crossbar was saturated at the MMA floor). 3-stage cp.async
// pipeline, 1 syncthreads per chunk, 2 CTAs/SM.

#define DD    128
#define NTOT  8192
#define KCAT  384
#define BN    128
#define BM    128
#define KC    64
#define NCH   (KCAT / KC)            // 6

#define ASZ   (128 * 128)            // 16384 B: one matrix, one stage
#define STG   (2 * ASZ)              // 32768: A + B per stage
#define SM_CN (3 * STG)              // 98304
#define SM_CM (SM_CN + 512)
#define SM_RS (SM_CM + 512)
#define SMEM_TOTAL (SM_RS + 512)     // 99840

__device__ __align__(16) __nv_bfloat16 g_xcat[NTOT * KCAT];
__device__ __align__(16) __nv_bfloat16 g_dcat[NTOT * KCAT];
__device__ float g_xn2[NTOT];
__device__ float g_dn2[NTOT];

// --------------------------------------------------------------- PTX helpers
__device__ __forceinline__ uint32_t smem_u32(const void* p) {
    uint32_t a;
    asm("{ .reg .u64 t; cvta.to.shared.u64 t, %1; cvt.u32.u64 %0, t; }"
        : "=r"(a) : "l"(p));
    return a;
}

__device__ __forceinline__ void cp_async16(uint32_t sa, const void* ga) {
    asm volatile("cp.async.cg.shared.global [%0], [%1], 16;"
                 :: "r"(sa), "l"(ga) : "memory");
}
#define CP_COMMIT() asm volatile("cp.async.commit_group;" ::: "memory")

__device__ __forceinline__ float fast_ex2(float x) {
    float y;
    asm("ex2.approx.f32 %0, %1;" : "=f"(y) : "f"(x));
    return y;
}

#define LDMX4(r0, r1, r2, r3, adr)                                            \
    asm volatile("ldmatrix.sync.aligned.m8n8.x4.shared.b16 {%0,%1,%2,%3}, [%4];" \
                 : "=r"(r0), "=r"(r1), "=r"(r2), "=r"(r3) : "r"(adr))

#define MMA16816(cc, a0, a1, a2, a3, b0, b1)                                  \
    asm volatile("mma.sync.aligned.m16n8k16.row.col.f32.bf16.bf16.f32 "       \
                 "{%0,%1,%2,%3},{%4,%5,%6,%7},{%8,%9},{%0,%1,%2,%3};"         \
                 : "+f"((cc)[0]), "+f"((cc)[1]), "+f"((cc)[2]), "+f"((cc)[3]) \
                 : "r"(a0), "r"(a1), "r"(a2), "r"(a3), "r"(b0), "r"(b1))

// -------------------------------------------------- convert + norms (warp/row)
__global__ void convert_kernel(const float* __restrict__ x,
                               const float* __restrict__ d) {
    const int gw   = (blockIdx.x * blockDim.x + threadIdx.x) >> 5;
    const int lane = threadIdx.x & 31;
    if (gw >= NTOT) return;

    {   // x row: [hi | hi | lo]
        float4 v = reinterpret_cast<const float4*>(x + (size_t)gw * DD)[lane];
        float nrm = v.x * v.x;
        nrm = fmaf(v.y, v.y, nrm);
        nrm = fmaf(v.z, v.z, nrm);
        nrm = fmaf(v.w, v.w, nrm);
        #pragma unroll
        for (int off = 16; off > 0; off >>= 1)
            nrm += __shfl_xor_sync(0xffffffffu, nrm, off);
        if (lane == 0) g_xn2[gw] = nrm;

        float f[4] = {v.x, v.y, v.z, v.w};
        unsigned short hb[4], lb[4];
        #pragma unroll
        for (int j = 0; j < 4; j++) {
            __nv_bfloat16 h = __float2bfloat16_rn(f[j]);
            __nv_bfloat16 l = __float2bfloat16_rn(f[j] - __bfloat162float(h));
            hb[j] = __bfloat16_as_ushort(h);
            lb[j] = __bfloat16_as_ushort(l);
        }
        uint2 hp = make_uint2((uint32_t)hb[0] | ((uint32_t)hb[1] << 16),
                              (uint32_t)hb[2] | ((uint32_t)hb[3] << 16));
        uint2 lp = make_uint2((uint32_t)lb[0] | ((uint32_t)lb[1] << 16),
                              (uint32_t)lb[2] | ((uint32_t)lb[3] << 16));
        char* base = reinterpret_cast<char*>(g_xcat) + (size_t)gw * 768 + lane * 8;
        *reinterpret_cast<uint2*>(base)       = hp;
        *reinterpret_cast<uint2*>(base + 256) = hp;
        *reinterpret_cast<uint2*>(base + 512) = lp;
    }
    {   // d row: [hi | lo | hi]
        float4 v = reinterpret_cast<const float4*>(d + (size_t)gw * DD)[lane];
        float nrm = v.x * v.x;
        nrm = fmaf(v.y, v.y, nrm);
        nrm = fmaf(v.z, v.z, nrm);
        nrm = fmaf(v.w, v.w, nrm);
        #pragma unroll
        for (int off = 16; off > 0; off >>= 1)
            nrm += __shfl_xor_sync(0xffffffffu, nrm, off);
        if (lane == 0) g_dn2[gw] = nrm;

        float f[4] = {v.x, v.y, v.z, v.w};
        unsigned short hb[4], lb[4];
        #pragma unroll
        for (int j = 0; j < 4; j++) {
            __nv_bfloat16 h = __float2bfloat16_rn(f[j]);
            __nv_bfloat16 l = __float2bfloat16_rn(f[j] - __bfloat162float(h));
            hb[j] = __bfloat16_as_ushort(h);
            lb[j] = __bfloat16_as_ushort(l);
        }
        uint2 hp = make_uint2((uint32_t)hb[0] | ((uint32_t)hb[1] << 16),
                              (uint32_t)hb[2] | ((uint32_t)hb[3] << 16));
        uint2 lp = make_uint2((uint32_t)lb[0] | ((uint32_t)lb[1] << 16),
                              (uint32_t)lb[2] | ((uint32_t)lb[3] << 16));
        char* base = reinterpret_cast<char*>(g_dcat) + (size_t)gw * 768 + lane * 8;
        *reinterpret_cast<uint2*>(base)       = hp;
        *reinterpret_cast<uint2*>(base + 256) = lp;
        *reinterpret_cast<uint2*>(base + 512) = hp;
    }
}

// ---------------------------------------------------------------- main kernel
__global__ void __launch_bounds__(128, 2)
kde_kernel(float* __restrict__ out) {
    extern __shared__ char smem[];
    const uint32_t sb = smem_u32(smem);
    const int tid  = threadIdx.x;
    const int lane = tid & 31;
    const int wid  = tid >> 5;
    const int wr   = wid & 1;      // n half (64 rows)
    const int wc   = wid >> 1;     // m half (64 cols)
    const int n0   = blockIdx.y * BN;
    const int m0   = blockIdx.x * BM;

    const float KEXP = -0.28777602743432504f;
    const float K2   =  0.57555205486865008f;

    float* cnS = reinterpret_cast<float*>(smem + SM_CN);
    float* cmS = reinterpret_cast<float*>(smem + SM_CM);
    float* rsS = reinterpret_cast<float*>(smem + SM_RS);

    cnS[tid] = KEXP * g_xn2[n0 + tid];
    cmS[tid] = KEXP * g_dn2[m0 + tid];
    rsS[tid] = 0.f;

    float c[4][8][4];
    #pragma unroll
    for (int rt = 0; rt < 4; rt++)
        #pragma unroll
        for (int ct = 0; ct < 8; ct++)
            #pragma unroll
            for (int q = 0; q < 4; q++)
                c[rt][ct][q] = 0.f;

    // ---- per-thread cp.async bases: 128 threads cover 128 rows x 8 segs ----
    const int row0 = tid >> 3;           // 0..15, covers rows row0+16*i
    const int w    = tid & 7;            // 16B segment within 128B k-chunk
    const char* gA0 = reinterpret_cast<const char*>(g_xcat) +
                      (size_t)(n0 + row0) * 768 + w * 16;
    const char* gB0 = reinterpret_cast<const char*>(g_dcat) +
                      (size_t)(m0 + row0) * 768 + w * 16;
    // swizzle term is i-invariant: (row0+16i)&7 == row0&7
    const uint32_t soff0 = row0 * 128 + ((w ^ (row0 & 7)) << 4);

    // ---- LDSM bases + precomputed swizzled k offsets ----
    const int h    = lane >> 4;
    const int rA   = wr * 64 + (lane & 15);
    const int rB   = wc * 64 + (lane & 15);
    const uint32_t sA0 = sb + rA * 128;          // + s*STG per stage
    const uint32_t sB0 = sb + ASZ + rB * 128;
    uint32_t kxA[4], kxB[4];
    #pragma unroll
    for (int k = 0; k < 4; k++) {
        kxA[k] = (uint32_t)(((2 * k + h) ^ (rA & 7)) << 4);
        kxB[k] = (uint32_t)(((2 * k + h) ^ (rB & 7)) << 4);
    }

    auto load_chunk = [&](int ch, int s) {
        const char* pa = gA0 + ch * 128;
        const char* pb = gB0 + ch * 128;
        const uint32_t da = sb + s * STG + soff0;
        const uint32_t db = da + ASZ;
        #pragma unroll
        for (int i = 0; i < 8; i++) {
            cp_async16(da + i * 2048, pa + (size_t)i * 12288);
            cp_async16(db + i * 2048, pb + (size_t)i * 12288);
        }
        CP_COMMIT();
    };

    auto compute_stage = [&](uint32_t sA, uint32_t sB) {
        #pragma unroll
        for (int k = 0; k < 4; k++) {
            uint32_t a[4][4];
            #pragma unroll
            for (int rt = 0; rt < 4; rt++)
                LDMX4(a[rt][0], a[rt][1], a[rt][2], a[rt][3],
                      sA + kxA[k] + rt * 2048);
            uint32_t b[8][2];
            #pragma unroll
            for (int p = 0; p < 4; p++) {
                uint32_t r0, r1, r2, r3;
                LDMX4(r0, r1, r2, r3, sB + kxB[k] + p * 2048);
                b[2 * p][0] = r0;     b[2 * p][1] = r2;
                b[2 * p + 1][0] = r1; b[2 * p + 1][1] = r3;
            }
            #pragma unroll
            for (int rt = 0; rt < 4; rt++)
                #pragma unroll
                for (int ct = 0; ct < 8; ct++)
                    MMA16816(c[rt][ct], a[rt][0], a[rt][1], a[rt][2], a[rt][3],
                             b[ct][0], b[ct][1]);
        }
    };

    // ---- 3-stage pipeline, fully unrolled, one __syncthreads per chunk ----
    load_chunk(0, 0);
    load_chunk(1, 1);

    #pragma unroll
    for (int ch = 0; ch < NCH; ch++) {
        if (ch < NCH - 1)
            asm volatile("cp.async.wait_group 1;" ::: "memory");
        else
            asm volatile("cp.async.wait_group 0;" ::: "memory");
        __syncthreads();
        const int s = ch % 3;
        compute_stage(sA0 + s * STG, sB0 + s * STG);
        if (ch + 2 < NCH) load_chunk(ch + 2, (ch + 2) % 3);
    }

    // --------- fused epilogue: exp2 + row reduce ---------
    const int rq = lane >> 2;
    const int cq = 2 * (lane & 3);
    #pragma unroll
    for (int rt = 0; rt < 4; rt++) {
        const int rbase = wr * 64 + rt * 16 + rq;
        const float cn0 = cnS[rbase];
        const float cn1 = cnS[rbase + 8];
        float s0 = 0.f, s1 = 0.f;
        #pragma unroll
        for (int ct = 0; ct < 8; ct++) {
            const int col = wc * 64 + ct * 8 + cq;
            const float cm0 = cmS[col], cm1 = cmS[col + 1];
            s0 += fast_ex2(fmaf(c[rt][ct][0], K2, cn0 + cm0));
            s0 += fast_ex2(fmaf(c[rt][ct][1], K2, cn0 + cm1));
            s1 += fast_ex2(fmaf(c[rt][ct][2], K2, cn1 + cm0));
            s1 += fast_ex2(fmaf(c[rt][ct][3], K2, cn1 + cm1));
        }
        s0 += __shfl_xor_sync(0xffffffffu, s0, 1);
        s0 += __shfl_xor_sync(0xffffffffu, s0, 2);
        s1 += __shfl_xor_sync(0xffffffffu, s1, 1);
        s1 += __shfl_xor_sync(0xffffffffu, s1, 2);
        if ((lane & 3) == 0) {
            atomicAdd(&rsS[rbase], s0);
            atomicAdd(&rsS[rbase + 8], s1);
        }
    }
    __syncthreads();
    atomicAdd(&out[n0 + tid], rsS[tid] * (1.0f / (float)NTOT));
}

extern "C" void kernel_launch(void* const* d_in, const int* in_sizes, int n_in,
                              void* d_out, int out_size) {
    const float* x    = (const float*)d_in[0];
    const float* data = (const float*)d_in[1];
    float* out = (float*)d_out;

    cudaFuncSetAttribute(kde_kernel,
                         cudaFuncAttributeMaxDynamicSharedMemorySize, SMEM_TOTAL);

    cudaMemsetAsync(d_out, 0, (size_t)out_size * sizeof(float));
    convert_kernel<<<NTOT * 32 / 256, 256>>>(x, data);

    dim3 grid(NTOT / BM, NTOT / BN);
    kde_kernel<<<grid, 128, SMEM_TOTAL>>>(out);
}

// round 15
// speedup vs baseline: 1.0314x; 1.0314x over previous
#include <cuda_runtime.h>
#include <cuda_bf16.h>
#include <cstdint>

// KDE via bf16 HMMA (mma.sync m16n8k16) GEMM over K=384 (2-term fp32 split):
//   Xcat[n] = [hiX | hiX | loX], Dcat[m] = [hiD | loD | hiD]
// density[n] = (1/M) * sum_m exp2( KEXP*(||x||^2+||d||^2) + K2*dot )
// R14: R8 base (256 thr, 64x32 warp tile, 2 CTAs/SM, 3-stage cp.async) +
// fully software-pipelined fragments (a rotates 2-deep prefetched one rt
// ahead; b prefetched one k ahead) + chunk loads issued before compute.

#define DD    128
#define NTOT  8192
#define KCAT  384
#define BN    128
#define BM    128
#define KC    64
#define NCH   (KCAT / KC)            // 6

#define ASZ   (128 * 128)            // 16384 B: one matrix, one stage
#define STG   (2 * ASZ)              // 32768: A + B per stage
#define SM_CN (3 * STG)              // 98304
#define SM_CM (SM_CN + 512)
#define SM_RS (SM_CM + 512)
#define SMEM_TOTAL (SM_RS + 512)     // 99840

__device__ __align__(16) __nv_bfloat16 g_xcat[NTOT * KCAT];
__device__ __align__(16) __nv_bfloat16 g_dcat[NTOT * KCAT];
__device__ float g_xn2[NTOT];
__device__ float g_dn2[NTOT];

// --------------------------------------------------------------- PTX helpers
__device__ __forceinline__ uint32_t smem_u32(const void* p) {
    uint32_t a;
    asm("{ .reg .u64 t; cvta.to.shared.u64 t, %1; cvt.u32.u64 %0, t; }"
        : "=r"(a) : "l"(p));
    return a;
}

__device__ __forceinline__ void cp_async16(uint32_t sa, const void* ga) {
    asm volatile("cp.async.cg.shared.global [%0], [%1], 16;"
                 :: "r"(sa), "l"(ga) : "memory");
}
#define CP_COMMIT() asm volatile("cp.async.commit_group;" ::: "memory")

__device__ __forceinline__ float fast_ex2(float x) {
    float y;
    asm("ex2.approx.f32 %0, %1;" : "=f"(y) : "f"(x));
    return y;
}

#define LDMX4(r0, r1, r2, r3, adr)                                            \
    asm volatile("ldmatrix.sync.aligned.m8n8.x4.shared.b16 {%0,%1,%2,%3}, [%4];" \
                 : "=r"(r0), "=r"(r1), "=r"(r2), "=r"(r3) : "r"(adr))

#define MMA16816(cc, a0, a1, a2, a3, b0, b1)                                  \
    asm volatile("mma.sync.aligned.m16n8k16.row.col.f32.bf16.bf16.f32 "       \
                 "{%0,%1,%2,%3},{%4,%5,%6,%7},{%8,%9},{%0,%1,%2,%3};"         \
                 : "+f"((cc)[0]), "+f"((cc)[1]), "+f"((cc)[2]), "+f"((cc)[3]) \
                 : "r"(a0), "r"(a1), "r"(a2), "r"(a3), "r"(b0), "r"(b1))

#define LD_B2(bb, adr) do {                                                   \
    uint32_t r0_, r1_, r2_, r3_;                                              \
    LDMX4(r0_, r1_, r2_, r3_, (adr));                                         \
    (bb)[0][0] = r0_; (bb)[0][1] = r2_; (bb)[1][0] = r1_; (bb)[1][1] = r3_;   \
    LDMX4(r0_, r1_, r2_, r3_, (adr) + 2048);                                  \
    (bb)[2][0] = r0_; (bb)[2][1] = r2_; (bb)[3][0] = r1_; (bb)[3][1] = r3_;   \
} while (0)

// -------------------------------------------------- convert + norms (warp/row)
__global__ void convert_kernel(const float* __restrict__ x,
                               const float* __restrict__ d) {
    const int gw   = (blockIdx.x * blockDim.x + threadIdx.x) >> 5;
    const int lane = threadIdx.x & 31;
    if (gw >= NTOT) return;

    {   // x row: [hi | hi | lo]
        float4 v = reinterpret_cast<const float4*>(x + (size_t)gw * DD)[lane];
        float nrm = v.x * v.x;
        nrm = fmaf(v.y, v.y, nrm);
        nrm = fmaf(v.z, v.z, nrm);
        nrm = fmaf(v.w, v.w, nrm);
        #pragma unroll
        for (int off = 16; off > 0; off >>= 1)
            nrm += __shfl_xor_sync(0xffffffffu, nrm, off);
        if (lane == 0) g_xn2[gw] = nrm;

        float f[4] = {v.x, v.y, v.z, v.w};
        unsigned short hb[4], lb[4];
        #pragma unroll
        for (int j = 0; j < 4; j++) {
            __nv_bfloat16 h = __float2bfloat16_rn(f[j]);
            __nv_bfloat16 l = __float2bfloat16_rn(f[j] - __bfloat162float(h));
            hb[j] = __bfloat16_as_ushort(h);
            lb[j] = __bfloat16_as_ushort(l);
        }
        uint2 hp = make_uint2((uint32_t)hb[0] | ((uint32_t)hb[1] << 16),
                              (uint32_t)hb[2] | ((uint32_t)hb[3] << 16));
        uint2 lp = make_uint2((uint32_t)lb[0] | ((uint32_t)lb[1] << 16),
                              (uint32_t)lb[2] | ((uint32_t)lb[3] << 16));
        char* base = reinterpret_cast<char*>(g_xcat) + (size_t)gw * 768 + lane * 8;
        *reinterpret_cast<uint2*>(base)       = hp;
        *reinterpret_cast<uint2*>(base + 256) = hp;
        *reinterpret_cast<uint2*>(base + 512) = lp;
    }
    {   // d row: [hi | lo | hi]
        float4 v = reinterpret_cast<const float4*>(d + (size_t)gw * DD)[lane];
        float nrm = v.x * v.x;
        nrm = fmaf(v.y, v.y, nrm);
        nrm = fmaf(v.z, v.z, nrm);
        nrm = fmaf(v.w, v.w, nrm);
        #pragma unroll
        for (int off = 16; off > 0; off >>= 1)
            nrm += __shfl_xor_sync(0xffffffffu, nrm, off);
        if (lane == 0) g_dn2[gw] = nrm;

        float f[4] = {v.x, v.y, v.z, v.w};
        unsigned short hb[4], lb[4];
        #pragma unroll
        for (int j = 0; j < 4; j++) {
            __nv_bfloat16 h = __float2bfloat16_rn(f[j]);
            __nv_bfloat16 l = __float2bfloat16_rn(f[j] - __bfloat162float(h));
            hb[j] = __bfloat16_as_ushort(h);
            lb[j] = __bfloat16_as_ushort(l);
        }
        uint2 hp = make_uint2((uint32_t)hb[0] | ((uint32_t)hb[1] << 16),
                              (uint32_t)hb[2] | ((uint32_t)hb[3] << 16));
        uint2 lp = make_uint2((uint32_t)lb[0] | ((uint32_t)lb[1] << 16),
                              (uint32_t)lb[2] | ((uint32_t)lb[3] << 16));
        char* base = reinterpret_cast<char*>(g_dcat) + (size_t)gw * 768 + lane * 8;
        *reinterpret_cast<uint2*>(base)       = hp;
        *reinterpret_cast<uint2*>(base + 256) = lp;
        *reinterpret_cast<uint2*>(base + 512) = hp;
    }
}

// ---------------------------------------------------------------- main kernel
__global__ void __launch_bounds__(256, 2)
kde_kernel(float* __restrict__ out) {
    extern __shared__ char smem[];
    const uint32_t sb = smem_u32(smem);
    const int tid  = threadIdx.x;
    const int lane = tid & 31;
    const int wid  = tid >> 5;
    const int wr   = wid & 1;      // n half (64 rows)
    const int wc   = wid >> 1;     // m quarter (32 cols)
    const int n0   = blockIdx.y * BN;
    const int m0   = blockIdx.x * BM;

    const float KEXP = -0.28777602743432504f;
    const float K2   =  0.57555205486865008f;

    float* cnS = reinterpret_cast<float*>(smem + SM_CN);
    float* cmS = reinterpret_cast<float*>(smem + SM_CM);
    float* rsS = reinterpret_cast<float*>(smem + SM_RS);

    if (tid < 128) {
        cnS[tid] = KEXP * g_xn2[n0 + tid];
        cmS[tid] = KEXP * g_dn2[m0 + tid];
        rsS[tid] = 0.f;
    }

    float c[4][4][4];
    #pragma unroll
    for (int rt = 0; rt < 4; rt++)
        #pragma unroll
        for (int ct = 0; ct < 4; ct++)
            #pragma unroll
            for (int q = 0; q < 4; q++)
                c[rt][ct][q] = 0.f;

    // ---- per-thread cp.async bases (all further addressing is immediate) ----
    const int row0 = tid >> 3;           // 0..31 (covers rows row0+32*i)
    const int w    = tid & 7;            // 16B segment within 128B k-chunk
    const char* gA0 = reinterpret_cast<const char*>(g_xcat) +
                      (size_t)(n0 + row0) * 768 + w * 16;
    const char* gB0 = reinterpret_cast<const char*>(g_dcat) +
                      (size_t)(m0 + row0) * 768 + w * 16;
    const uint32_t soff0 = row0 * 128 + ((w ^ (row0 & 7)) << 4);

    // ---- LDSM bases + precomputed swizzled k offsets ----
    const int h    = lane >> 4;
    const int rA   = wr * 64 + (lane & 15);
    const int rB   = wc * 32 + (lane & 15);
    const uint32_t sA0 = sb + rA * 128;          // + s*STG per stage
    const uint32_t sB0 = sb + ASZ + rB * 128;
    uint32_t kxA[4], kxB[4];
    #pragma unroll
    for (int k = 0; k < 4; k++) {
        kxA[k] = (uint32_t)(((2 * k + h) ^ (rA & 7)) << 4);
        kxB[k] = (uint32_t)(((2 * k + h) ^ (rB & 7)) << 4);
    }

    auto load_chunk = [&](int ch, int s) {
        const char* pa = gA0 + ch * 128;
        const char* pb = gB0 + ch * 128;
        const uint32_t da = sb + s * STG + soff0;
        const uint32_t db = da + ASZ;
        #pragma unroll
        for (int i = 0; i < 4; i++) {
            cp_async16(da + i * 4096, pa + (size_t)i * 24576);
            cp_async16(db + i * 4096, pb + (size_t)i * 24576);
        }
        CP_COMMIT();
    };

    // ---- software-pipelined compute: a rotates 2-deep, b 2-deep by k ----
    auto compute_stage = [&](uint32_t sA, uint32_t sB) {
        uint32_t aa[2][4];
        uint32_t bb[2][4][2];
        LD_B2(bb[0], sB + kxB[0]);
        LDMX4(aa[0][0], aa[0][1], aa[0][2], aa[0][3], sA + kxA[0]);
        #pragma unroll
        for (int k = 0; k < 4; k++) {
            #pragma unroll
            for (int rt = 0; rt < 4; rt++) {
                const int cur = rt & 1;
                if (rt < 3) {
                    LDMX4(aa[cur ^ 1][0], aa[cur ^ 1][1],
                          aa[cur ^ 1][2], aa[cur ^ 1][3],
                          sA + kxA[k] + (rt + 1) * 2048);
                } else if (k < 3) {
                    LDMX4(aa[cur ^ 1][0], aa[cur ^ 1][1],
                          aa[cur ^ 1][2], aa[cur ^ 1][3],
                          sA + kxA[k + 1]);
                }
                if (rt == 0 && k < 3)
                    LD_B2(bb[(k + 1) & 1], sB + kxB[k + 1]);
                #pragma unroll
                for (int ct = 0; ct < 4; ct++)
                    MMA16816(c[rt][ct],
                             aa[cur][0], aa[cur][1], aa[cur][2], aa[cur][3],
                             bb[k & 1][ct][0], bb[k & 1][ct][1]);
            }
        }
    };

    // ---- 3-stage pipeline, loads issued before compute, 1 sync per chunk ----
    load_chunk(0, 0);
    load_chunk(1, 1);

    #pragma unroll
    for (int ch = 0; ch < NCH; ch++) {
        if (ch < NCH - 1)
            asm volatile("cp.async.wait_group 1;" ::: "memory");
        else
            asm volatile("cp.async.wait_group 0;" ::: "memory");
        __syncthreads();
        if (ch + 2 < NCH) load_chunk(ch + 2, (ch + 2) % 3);
        const int s = ch % 3;
        compute_stage(sA0 + s * STG, sB0 + s * STG);
    }

    // --------- fused epilogue: exp2 + row reduce ---------
    const int rq = lane >> 2;
    const int cq = 2 * (lane & 3);
    #pragma unroll
    for (int rt = 0; rt < 4; rt++) {
        const int rbase = wr * 64 + rt * 16 + rq;
        const float cn0 = cnS[rbase];
        const float cn1 = cnS[rbase + 8];
        float s0 = 0.f, s1 = 0.f;
        #pragma unroll
        for (int ct = 0; ct < 4; ct++) {
            const int col = wc * 32 + ct * 8 + cq;
            const float cm0 = cmS[col], cm1 = cmS[col + 1];
            s0 += fast_ex2(fmaf(c[rt][ct][0], K2, cn0 + cm0));
            s0 += fast_ex2(fmaf(c[rt][ct][1], K2, cn0 + cm1));
            s1 += fast_ex2(fmaf(c[rt][ct][2], K2, cn1 + cm0));
            s1 += fast_ex2(fmaf(c[rt][ct][3], K2, cn1 + cm1));
        }
        s0 += __shfl_xor_sync(0xffffffffu, s0, 1);
        s0 += __shfl_xor_sync(0xffffffffu, s0, 2);
        s1 += __shfl_xor_sync(0xffffffffu, s1, 1);
        s1 += __shfl_xor_sync(0xffffffffu, s1, 2);
        if ((lane & 3) == 0) {
            atomicAdd(&rsS[rbase], s0);
            atomicAdd(&rsS[rbase + 8], s1);
        }
    }
    __syncthreads();
    if (tid < 128)
        atomicAdd(&out[n0 + tid], rsS[tid] * (1.0f / (float)NTOT));
}

extern "C" void kernel_launch(void* const* d_in, const int* in_sizes, int n_in,
                              void* d_out, int out_size) {
    const float* x    = (const float*)d_in[0];
    const float* data = (const float*)d_in[1];
    float* out = (float*)d_out;

    cudaFuncSetAttribute(kde_kernel,
                         cudaFuncAttributeMaxDynamicSharedMemorySize, SMEM_TOTAL);

    cudaMemsetAsync(d_out, 0, (size_t)out_size * sizeof(float));
    convert_kernel<<<NTOT * 32 / 256, 256>>>(x, data);

    dim3 grid(NTOT / BM, NTOT / BN);
    kde_kernel<<<grid, 256, SMEM_TOTAL>>>(out);
}

// round 17
// speedup vs baseline: 1.0689x; 1.0364x over previous
#include <cuda_runtime.h>
#include <cuda_bf16.h>
#include <cstdint>

// KDE via bf16 HMMA (mma.sync m16n8k16) GEMM over K=384 (2-term fp32 split):
//   Xcat[n] = [hiX | hiX | loX], Dcat[m] = K2 * [hiD | loD | hiD]
// (K2 folded into D, so the GEMM accumulator holds K2*dot directly.)
// density[n] = (1/M) * sum_m ex2(K2*dot) * em[m] * fx[n]
//   em[m] = ex2(KEXP*||d||^2)  (precomputed, smem)
//   fx[n] = ex2(KEXP*||x||^2)  (applied once per row)
// R15: R8 GEMM core + factorized exponential epilogue (MUFU+FFMA per element).

#define DD    128
#define NTOT  8192
#define KCAT  384
#define BN    128
#define BM    128
#define KC    64
#define NCH   (KCAT / KC)            // 6

#define ASZ   (128 * 128)            // 16384 B: one matrix, one stage
#define STG   (2 * ASZ)              // 32768: A + B per stage
#define SM_CN (3 * STG)              // 98304
#define SM_EM (SM_CN + 512)
#define SM_RS (SM_EM + 512)
#define SMEM_TOTAL (SM_RS + 512)     // 99840

__device__ __align__(16) __nv_bfloat16 g_xcat[NTOT * KCAT];
__device__ __align__(16) __nv_bfloat16 g_dcat[NTOT * KCAT];
__device__ float g_xn2[NTOT];
__device__ float g_dn2[NTOT];

// --------------------------------------------------------------- PTX helpers
__device__ __forceinline__ uint32_t smem_u32(const void* p) {
    uint32_t a;
    asm("{ .reg .u64 t; cvta.to.shared.u64 t, %1; cvt.u32.u64 %0, t; }"
        : "=r"(a) : "l"(p));
    return a;
}

__device__ __forceinline__ void cp_async16(uint32_t sa, const void* ga) {
    asm volatile("cp.async.cg.shared.global [%0], [%1], 16;"
                 :: "r"(sa), "l"(ga) : "memory");
}
#define CP_COMMIT() asm volatile("cp.async.commit_group;" ::: "memory")

__device__ __forceinline__ float fast_ex2(float x) {
    float y;
    asm("ex2.approx.f32 %0, %1;" : "=f"(y) : "f"(x));
    return y;
}

#define LDMX4(r0, r1, r2, r3, adr)                                            \
    asm volatile("ldmatrix.sync.aligned.m8n8.x4.shared.b16 {%0,%1,%2,%3}, [%4];" \
                 : "=r"(r0), "=r"(r1), "=r"(r2), "=r"(r3) : "r"(adr))

#define MMA16816(cc, a0, a1, a2, a3, b0, b1)                                  \
    asm volatile("mma.sync.aligned.m16n8k16.row.col.f32.bf16.bf16.f32 "       \
                 "{%0,%1,%2,%3},{%4,%5,%6,%7},{%8,%9},{%0,%1,%2,%3};"         \
                 : "+f"((cc)[0]), "+f"((cc)[1]), "+f"((cc)[2]), "+f"((cc)[3]) \
                 : "r"(a0), "r"(a1), "r"(a2), "r"(a3), "r"(b0), "r"(b1))

#define LD_B(bb, adr) do {                                                    \
    uint32_t r0_, r1_, r2_, r3_;                                              \
    LDMX4(r0_, r1_, r2_, r3_, (adr));                                         \
    (bb)[0][0] = r0_; (bb)[0][1] = r2_; (bb)[1][0] = r1_; (bb)[1][1] = r3_;   \
    LDMX4(r0_, r1_, r2_, r3_, (adr) + 2048);                                  \
    (bb)[2][0] = r0_; (bb)[2][1] = r2_; (bb)[3][0] = r1_; (bb)[3][1] = r3_;   \
} while (0)

#define LD_A(aa, adr) do {                                                    \
    LDMX4((aa)[0][0], (aa)[0][1], (aa)[0][2], (aa)[0][3], (adr));             \
    LDMX4((aa)[1][0], (aa)[1][1], (aa)[1][2], (aa)[1][3], (adr) + 2048);      \
    LDMX4((aa)[2][0], (aa)[2][1], (aa)[2][2], (aa)[2][3], (adr) + 4096);      \
    LDMX4((aa)[3][0], (aa)[3][1], (aa)[3][2], (aa)[3][3], (adr) + 6144);      \
} while (0)

// -------------------------------------------------- convert + norms (warp/row)
__global__ void convert_kernel(const float* __restrict__ x,
                               const float* __restrict__ d) {
    const int gw   = (blockIdx.x * blockDim.x + threadIdx.x) >> 5;
    const int lane = threadIdx.x & 31;
    if (gw >= NTOT) return;
    const float K2 = 0.57555205486865008f;   // -2*KEXP

    {   // x row: [hi | hi | lo]  (unscaled)
        float4 v = reinterpret_cast<const float4*>(x + (size_t)gw * DD)[lane];
        float nrm = v.x * v.x;
        nrm = fmaf(v.y, v.y, nrm);
        nrm = fmaf(v.z, v.z, nrm);
        nrm = fmaf(v.w, v.w, nrm);
        #pragma unroll
        for (int off = 16; off > 0; off >>= 1)
            nrm += __shfl_xor_sync(0xffffffffu, nrm, off);
        if (lane == 0) g_xn2[gw] = nrm;

        float f[4] = {v.x, v.y, v.z, v.w};
        unsigned short hb[4], lb[4];
        #pragma unroll
        for (int j = 0; j < 4; j++) {
            __nv_bfloat16 h = __float2bfloat16_rn(f[j]);
            __nv_bfloat16 l = __float2bfloat16_rn(f[j] - __bfloat162float(h));
            hb[j] = __bfloat16_as_ushort(h);
            lb[j] = __bfloat16_as_ushort(l);
        }
        uint2 hp = make_uint2((uint32_t)hb[0] | ((uint32_t)hb[1] << 16),
                              (uint32_t)hb[2] | ((uint32_t)hb[3] << 16));
        uint2 lp = make_uint2((uint32_t)lb[0] | ((uint32_t)lb[1] << 16),
                              (uint32_t)lb[2] | ((uint32_t)lb[3] << 16));
        char* base = reinterpret_cast<char*>(g_xcat) + (size_t)gw * 768 + lane * 8;
        *reinterpret_cast<uint2*>(base)       = hp;
        *reinterpret_cast<uint2*>(base + 256) = hp;
        *reinterpret_cast<uint2*>(base + 512) = lp;
    }
    {   // d row: [hi | lo | hi], scaled by K2 (norm from unscaled d)
        float4 v = reinterpret_cast<const float4*>(d + (size_t)gw * DD)[lane];
        float nrm = v.x * v.x;
        nrm = fmaf(v.y, v.y, nrm);
        nrm = fmaf(v.z, v.z, nrm);
        nrm = fmaf(v.w, v.w, nrm);
        #pragma unroll
        for (int off = 16; off > 0; off >>= 1)
            nrm += __shfl_xor_sync(0xffffffffu, nrm, off);
        if (lane == 0) g_dn2[gw] = nrm;

        float f[4] = {K2 * v.x, K2 * v.y, K2 * v.z, K2 * v.w};
        unsigned short hb[4], lb[4];
        #pragma unroll
        for (int j = 0; j < 4; j++) {
            __nv_bfloat16 h = __float2bfloat16_rn(f[j]);
            __nv_bfloat16 l = __float2bfloat16_rn(f[j] - __bfloat162float(h));
            hb[j] = __bfloat16_as_ushort(h);
            lb[j] = __bfloat16_as_ushort(l);
        }
        uint2 hp = make_uint2((uint32_t)hb[0] | ((uint32_t)hb[1] << 16),
                              (uint32_t)hb[2] | ((uint32_t)hb[3] << 16));
        uint2 lp = make_uint2((uint32_t)lb[0] | ((uint32_t)lb[1] << 16),
                              (uint32_t)lb[2] | ((uint32_t)lb[3] << 16));
        char* base = reinterpret_cast<char*>(g_dcat) + (size_t)gw * 768 + lane * 8;
        *reinterpret_cast<uint2*>(base)       = hp;
        *reinterpret_cast<uint2*>(base + 256) = lp;
        *reinterpret_cast<uint2*>(base + 512) = hp;
    }
}

// ---------------------------------------------------------------- main kernel
__global__ void __launch_bounds__(256, 2)
kde_kernel(float* __restrict__ out) {
    extern __shared__ char smem[];
    const uint32_t sb = smem_u32(smem);
    const int tid  = threadIdx.x;
    const int lane = tid & 31;
    const int wid  = tid >> 5;
    const int wr   = wid & 1;      // n half (64 rows)
    const int wc   = wid >> 1;     // m quarter (32 cols)
    const int n0   = blockIdx.y * BN;
    const int m0   = blockIdx.x * BM;

    const float KEXP = -0.28777602743432504f;  // -(0.5/sqrt(2pi))*log2(e)

    float* cnS = reinterpret_cast<float*>(smem + SM_CN);  // KEXP*||x||^2
    float* emS = reinterpret_cast<float*>(smem + SM_EM);  // ex2(KEXP*||d||^2)
    float* rsS = reinterpret_cast<float*>(smem + SM_RS);

    if (tid < 128) {
        cnS[tid] = KEXP * g_xn2[n0 + tid];
        emS[tid] = fast_ex2(KEXP * g_dn2[m0 + tid]);
        rsS[tid] = 0.f;
    }

    float c[4][4][4];
    #pragma unroll
    for (int rt = 0; rt < 4; rt++)
        #pragma unroll
        for (int ct = 0; ct < 4; ct++)
            #pragma unroll
            for (int q = 0; q < 4; q++)
                c[rt][ct][q] = 0.f;

    // ---- per-thread cp.async bases (all further addressing is immediate) ----
    const int row0 = tid >> 3;           // 0..31 (covers rows row0+32*i)
    const int w    = tid & 7;            // 16B segment within 128B k-chunk
    const char* gA0 = reinterpret_cast<const char*>(g_xcat) +
                      (size_t)(n0 + row0) * 768 + w * 16;
    const char* gB0 = reinterpret_cast<const char*>(g_dcat) +
                      (size_t)(m0 + row0) * 768 + w * 16;
    const uint32_t soff0 = row0 * 128 + ((w ^ (row0 & 7)) << 4);

    // ---- LDSM bases + precomputed swizzled k offsets ----
    const int h    = lane >> 4;
    const int rA   = wr * 64 + (lane & 15);
    const int rB   = wc * 32 + (lane & 15);
    const uint32_t sA0 = sb + rA * 128;          // + s*STG per stage
    const uint32_t sB0 = sb + ASZ + rB * 128;
    uint32_t kxA[4], kxB[4];
    #pragma unroll
    for (int k = 0; k < 4; k++) {
        kxA[k] = (uint32_t)(((2 * k + h) ^ (rA & 7)) << 4);
        kxB[k] = (uint32_t)(((2 * k + h) ^ (rB & 7)) << 4);
    }

    auto load_chunk = [&](int ch, int s) {
        const char* pa = gA0 + ch * 128;
        const char* pb = gB0 + ch * 128;
        const uint32_t da = sb + s * STG + soff0;
        const uint32_t db = da + ASZ;
        #pragma unroll
        for (int i = 0; i < 4; i++) {
            cp_async16(da + i * 4096, pa + (size_t)i * 24576);
            cp_async16(db + i * 4096, pb + (size_t)i * 24576);
        }
        CP_COMMIT();
    };

    auto compute_stage = [&](uint32_t sA, uint32_t sB) {
        uint32_t b[2][4][2];
        LD_B(b[0], sB + kxB[0]);
        #pragma unroll
        for (int k = 0; k < 4; k++) {
            uint32_t a[4][4];
            LD_A(a, sA + kxA[k]);
            if (k < 3) LD_B(b[(k + 1) & 1], sB + kxB[k + 1]);
            const int cur = k & 1;
            #pragma unroll
            for (int rt = 0; rt < 4; rt++)
                #pragma unroll
                for (int ct = 0; ct < 4; ct++)
                    MMA16816(c[rt][ct], a[rt][0], a[rt][1], a[rt][2], a[rt][3],
                             b[cur][ct][0], b[cur][ct][1]);
        }
    };

    // ---- 3-stage pipeline, fully unrolled, one __syncthreads per chunk ----
    load_chunk(0, 0);
    load_chunk(1, 1);

    #pragma unroll
    for (int ch = 0; ch < NCH; ch++) {
        if (ch < NCH - 1)
            asm volatile("cp.async.wait_group 1;" ::: "memory");
        else
            asm volatile("cp.async.wait_group 0;" ::: "memory");
        __syncthreads();
        const int s = ch % 3;
        compute_stage(sA0 + s * STG, sB0 + s * STG);
        if (ch + 2 < NCH) load_chunk(ch + 2, (ch + 2) % 3);
    }

    // --------- fused epilogue: term = ex2(c) * em[col], row factor at end ---
    const int rq = lane >> 2;
    const int cq = 2 * (lane & 3);
    float em0[4], em1[4];
    #pragma unroll
    for (int ct = 0; ct < 4; ct++) {
        const int col = wc * 32 + ct * 8 + cq;
        em0[ct] = emS[col];
        em1[ct] = emS[col + 1];
    }
    #pragma unroll
    for (int rt = 0; rt < 4; rt++) {
        const int rbase = wr * 64 + rt * 16 + rq;
        float s0 = 0.f, s0b = 0.f, s1 = 0.f, s1b = 0.f;
        #pragma unroll
        for (int ct = 0; ct < 4; ct++) {
            s0  = fmaf(fast_ex2(c[rt][ct][0]), em0[ct], s0);
            s0b = fmaf(fast_ex2(c[rt][ct][1]), em1[ct], s0b);
            s1  = fmaf(fast_ex2(c[rt][ct][2]), em0[ct], s1);
            s1b = fmaf(fast_ex2(c[rt][ct][3]), em1[ct], s1b);
        }
        float s0t = s0 + s0b;
        float s1t = s1 + s1b;
        s0t += __shfl_xor_sync(0xffffffffu, s0t, 1);
        s0t += __shfl_xor_sync(0xffffffffu, s0t, 2);
        s1t += __shfl_xor_sync(0xffffffffu, s1t, 1);
        s1t += __shfl_xor_sync(0xffffffffu, s1t, 2);
        if ((lane & 3) == 0) {
            atomicAdd(&rsS[rbase],     s0t * fast_ex2(cnS[rbase]));
            atomicAdd(&rsS[rbase + 8], s1t * fast_ex2(cnS[rbase + 8]));
        }
    }
    __syncthreads();
    if (tid < 128)
        atomicAdd(&out[n0 + tid], rsS[tid] * (1.0f / (float)NTOT));
}

extern "C" void kernel_launch(void* const* d_in, const int* in_sizes, int n_in,
                              void* d_out, int out_size) {
    const float* x    = (const float*)d_in[0];
    const float* data = (const float*)d_in[1];
    float* out = (float*)d_out;

    cudaFuncSetAttribute(kde_kernel,
                         cudaFuncAttributeMaxDynamicSharedMemorySize, SMEM_TOTAL);

    cudaMemsetAsync(d_out, 0, (size_t)out_size * sizeof(float));
    convert_kernel<<<NTOT * 32 / 256, 256>>>(x, data);

    dim3 grid(NTOT / BM, NTOT / BN);
    kde_kernel<<<grid, 256, SMEM_TOTAL>>>(out);
}